// round 5
// baseline (speedup 1.0000x reference)
#include <cuda_runtime.h>
#include <cuda_fp16.h>
#include <mma.h>
#include <cstdint>
#include <math_constants.h>

using namespace nvcuda;

static constexpr int B = 8, S = 2048, D = 768;
static constexpr int M_TOT = B * S; // 16384

// ---------------------------------------------------------------------------
// Scratch (__device__ globals — allocation-free rule)
// ---------------------------------------------------------------------------
__device__ __half g_xh [(size_t)B * S * D];
__device__ __half g_xl [(size_t)B * S * D];
__device__ __half g_xTh[(size_t)B * S * D];   // [B, D, S]
__device__ __half g_Wh [D * D];
__device__ __half g_Wl [D * D];
__device__ __half g_pwh[D * D];
__device__ __half g_Wxh[(size_t)B * S * D];
__device__ __half g_Wxl[(size_t)B * S * D];
__device__ __half g_ah [(size_t)B * S * S];   // softmax output fp16
__device__ __half g_ch [(size_t)B * S * D];
__device__ float  g_s  [(size_t)B * S * S];   // logits fp32

// ---------------------------------------------------------------------------
// cp.async helpers
// ---------------------------------------------------------------------------
__device__ __forceinline__ uint32_t smem_u32(const void* p) {
    uint32_t a;
    asm("{ .reg .u64 t; cvta.to.shared.u64 t, %1; cvt.u32.u64 %0, t; }" : "=r"(a) : "l"(p));
    return a;
}
__device__ __forceinline__ void cp16(uint32_t saddr, const void* g) {
    asm volatile("cp.async.cg.shared.global [%0], [%1], 16;" :: "r"(saddr), "l"(g));
}
__device__ __forceinline__ void cp_commit() { asm volatile("cp.async.commit_group;" ::: "memory"); }
__device__ __forceinline__ void cp_wait1()  { asm volatile("cp.async.wait_group 1;" ::: "memory"); }

// ---------------------------------------------------------------------------
// hgemm: C[M,N] = A[M,K] * B[N,K]^T  (both operands K-contiguous fp16)
// Tiles 128x128, BK=32, 3-stage cp.async pipeline, 256 threads
// (8 warps, each 64x32 via wmma 16x16x16).
// Smem rows padded to LDH=40 halves (80B stride — conflict-free ldmatrix).
// SP3: 3-pass compensated product (Ah*Bh + Ah*Bl + Al*Bh).
// EPI: 0 = fp32 C (direct wmma store); 1 = split fp16 (Ch+Cl);
//      2 = fp16 Ch; 3 = fp32 resid + relu(C + bias)
// ---------------------------------------------------------------------------
static constexpr int BK = 32;
static constexpr int LDH = 40;                        // halves per smem row
static constexpr uint32_t TILE_B = 128 * LDH * 2;     // 10240 bytes per tile

template <bool SP3>
__device__ __forceinline__ void load_chunk(
    uint32_t sb, const __half* Ah, const __half* Al,
    const __half* Bh, const __half* Bl,
    int lda, int ldb, int rowBase, int colBase, int k0, int tid)
{
    #pragma unroll
    for (int i = 0; i < 2; ++i) {
        const int g = tid + i * 256;          // 512 granules of 16B per tile
        const int r = g >> 2;                 // 0..127
        const int c = g & 3;                  // 0..3 (8 halves each)
        const uint32_t off = (uint32_t)(r * (LDH * 2) + c * 16);
        const size_t ga = (size_t)(rowBase + r) * lda + k0 + c * 8;
        const size_t gb = (size_t)(colBase + r) * ldb + k0 + c * 8;
        cp16(sb + off, Ah + ga);
        if (SP3) cp16(sb + TILE_B + off, Al + ga);
        cp16(sb + (SP3 ? 2 : 1) * TILE_B + off, Bh + gb);
        if (SP3) cp16(sb + 3 * TILE_B + off, Bl + gb);
    }
}

template <bool SP3>
__device__ __forceinline__ void compute_chunk(
    const __half* sm,
    wmma::fragment<wmma::accumulator, 16, 16, 16, float> acc[4][2],
    int warp_m, int warp_n)
{
    const __half* As  = sm;
    const __half* Als = sm + 128 * LDH;
    const __half* Bs  = sm + (SP3 ? 2 : 1) * 128 * LDH;
    const __half* Bls = Bs + 128 * LDH;

    #pragma unroll
    for (int kk = 0; kk < BK / 16; ++kk) {
        // Load ALL fragments for this k-slice first (max MMA independence).
        wmma::fragment<wmma::matrix_b, 16, 16, 16, __half, wmma::col_major> bh[2], bl[2];
        wmma::fragment<wmma::matrix_a, 16, 16, 16, __half, wmma::row_major> ah[4], al[4];
        #pragma unroll
        for (int nj = 0; nj < 2; ++nj) {
            wmma::load_matrix_sync(bh[nj], Bs + (size_t)(warp_n + nj * 16) * LDH + kk * 16, LDH);
            if (SP3)
                wmma::load_matrix_sync(bl[nj], Bls + (size_t)(warp_n + nj * 16) * LDH + kk * 16, LDH);
        }
        #pragma unroll
        for (int mi = 0; mi < 4; ++mi) {
            wmma::load_matrix_sync(ah[mi], As + (size_t)(warp_m + mi * 16) * LDH + kk * 16, LDH);
            if (SP3)
                wmma::load_matrix_sync(al[mi], Als + (size_t)(warp_m + mi * 16) * LDH + kk * 16, LDH);
        }
        // Pass 1: Ah*Bh — 8 independent accumulators back-to-back
        #pragma unroll
        for (int mi = 0; mi < 4; ++mi)
            #pragma unroll
            for (int nj = 0; nj < 2; ++nj)
                wmma::mma_sync(acc[mi][nj], ah[mi], bh[nj], acc[mi][nj]);
        if (SP3) {
            // Pass 2: Ah*Bl
            #pragma unroll
            for (int mi = 0; mi < 4; ++mi)
                #pragma unroll
                for (int nj = 0; nj < 2; ++nj)
                    wmma::mma_sync(acc[mi][nj], ah[mi], bl[nj], acc[mi][nj]);
            // Pass 3: Al*Bh
            #pragma unroll
            for (int mi = 0; mi < 4; ++mi)
                #pragma unroll
                for (int nj = 0; nj < 2; ++nj)
                    wmma::mma_sync(acc[mi][nj], al[mi], bh[nj], acc[mi][nj]);
        }
    }
}

template <bool SP3, int EPI>
__global__ __launch_bounds__(256)
void hgemm(const __half* __restrict__ Ah, const __half* __restrict__ Al,
           const __half* __restrict__ Bh, const __half* __restrict__ Bl,
           float* __restrict__ Cf, __half* __restrict__ Ch, __half* __restrict__ Cl,
           const float* __restrict__ bias, const float* __restrict__ resid,
           int lda, int ldb, int ldc, int K,
           size_t sA, size_t sB, size_t sC)
{
    extern __shared__ char smem[];
    const uint32_t sb0 = smem_u32(smem);
    constexpr uint32_t BUF = TILE_B * (SP3 ? 4 : 2);

    const int tid = threadIdx.x, wid = tid >> 5;
    const int rowBase = blockIdx.y * 128;
    const int colBase = blockIdx.x * 128;
    const int warp_m = (wid >> 2) * 64;   // 0 or 64
    const int warp_n = (wid & 3) * 32;    // 0,32,64,96

    Ah += (size_t)blockIdx.z * sA;
    Bh += (size_t)blockIdx.z * sB;
    if (SP3) { Al += (size_t)blockIdx.z * sA; Bl += (size_t)blockIdx.z * sB; }

    wmma::fragment<wmma::accumulator, 16, 16, 16, float> acc[4][2];
    #pragma unroll
    for (int mi = 0; mi < 4; ++mi)
        #pragma unroll
        for (int nj = 0; nj < 2; ++nj)
            wmma::fill_fragment(acc[mi][nj], 0.0f);

    const int NK = K / BK;

    // 3-stage pipeline prologue
    load_chunk<SP3>(sb0 + 0 * BUF, Ah, Al, Bh, Bl, lda, ldb, rowBase, colBase, 0, tid);
    cp_commit();
    load_chunk<SP3>(sb0 + 1 * BUF, Ah, Al, Bh, Bl, lda, ldb, rowBase, colBase, BK, tid);
    cp_commit();

    int wbuf = 2;
    for (int ck = 0; ck < NK; ++ck) {
        cp_wait1();
        __syncthreads();                 // stage ck%3 ready; all warps done with buf being refilled
        if (ck + 2 < NK)
            load_chunk<SP3>(sb0 + wbuf * BUF, Ah, Al, Bh, Bl,
                            lda, ldb, rowBase, colBase, (ck + 2) * BK, tid);
        cp_commit();                     // unconditional commit keeps group accounting exact
        compute_chunk<SP3>((const __half*)(smem + (ck % 3) * BUF), acc, warp_m, warp_n);
        wbuf = wbuf == 2 ? 0 : wbuf + 1;
    }

    if (EPI == 0) {
        // direct fp32 store (GEMM2 path — the big output)
        #pragma unroll
        for (int mi = 0; mi < 4; ++mi)
            #pragma unroll
            for (int nj = 0; nj < 2; ++nj) {
                float* dst = (Cf + (size_t)blockIdx.z * sC)
                           + (size_t)(rowBase + warp_m + mi * 16) * ldc
                           + colBase + warp_n + nj * 16;
                wmma::store_matrix_sync(dst, acc[mi][nj], ldc, wmma::mem_row_major);
            }
        return;
    }

    // staged epilogue: park the 128x128 fp32 tile in smem, then transform.
    __syncthreads();
    float* stg = (float*)smem;
    #pragma unroll
    for (int mi = 0; mi < 4; ++mi)
        #pragma unroll
        for (int nj = 0; nj < 2; ++nj)
            wmma::store_matrix_sync(stg + (size_t)(warp_m + mi * 16) * 128 + warp_n + nj * 16,
                                    acc[mi][nj], 128, wmma::mem_row_major);
    __syncthreads();

    #pragma unroll
    for (int i = 0; i < 16; ++i) {
        const int idx = i * 256 + tid;   // 4096 float4 chunks
        const int el = idx * 4;
        const int row = el >> 7;
        const int col = el & 127;
        const float4 v = *(const float4*)(stg + el);
        const size_t m = (size_t)(rowBase + row);
        const int n = colBase + col;
        if (EPI == 1) {
            __half* ChB = Ch + (size_t)blockIdx.z * sC;
            __half* ClB = Cl + (size_t)blockIdx.z * sC;
            const __half h0 = __float2half_rn(v.x), h1 = __float2half_rn(v.y);
            const __half h2 = __float2half_rn(v.z), h3 = __float2half_rn(v.w);
            *(__half2*)(ChB + m * ldc + n)     = __halves2half2(h0, h1);
            *(__half2*)(ChB + m * ldc + n + 2) = __halves2half2(h2, h3);
            *(__half2*)(ClB + m * ldc + n) =
                __halves2half2(__float2half_rn(v.x - __half2float(h0)),
                               __float2half_rn(v.y - __half2float(h1)));
            *(__half2*)(ClB + m * ldc + n + 2) =
                __halves2half2(__float2half_rn(v.z - __half2float(h2)),
                               __float2half_rn(v.w - __half2float(h3)));
        } else if (EPI == 2) {
            __half* ChB = Ch + (size_t)blockIdx.z * sC;
            *(__half2*)(ChB + m * ldc + n)     = __halves2half2(__float2half_rn(v.x), __float2half_rn(v.y));
            *(__half2*)(ChB + m * ldc + n + 2) = __halves2half2(__float2half_rn(v.z), __float2half_rn(v.w));
        } else { // EPI == 3
            const float4 bb = *(const float4*)(bias + n);
            const float4 rr = *(const float4*)(resid + m * ldc + n);
            float4 o;
            o.x = fmaxf(v.x + bb.x, 0.f) + rr.x;
            o.y = fmaxf(v.y + bb.y, 0.f) + rr.y;
            o.z = fmaxf(v.z + bb.z, 0.f) + rr.z;
            o.w = fmaxf(v.w + bb.w, 0.f) + rr.w;
            *(float4*)(Cf + m * ldc + n) = o;
        }
    }
}

// ---------------------------------------------------------------------------
// Prep kernels
// ---------------------------------------------------------------------------
__global__ __launch_bounds__(256)
void prep_x_kernel(const float* __restrict__ x, __half* __restrict__ xh, __half* __restrict__ xl)
{
    const size_t i = (size_t)blockIdx.x * 256 + threadIdx.x;
    const size_t n = (size_t)B * S * D;
    if (i < n) {
        const float v = x[i];
        const __half h = __float2half_rn(v);
        xh[i] = h;
        xl[i] = __float2half_rn(v - __half2float(h));
    }
}

__global__ __launch_bounds__(256)
void prep_w_kernel(const float* __restrict__ W, const float* __restrict__ pw,
                   __half* __restrict__ Wh, __half* __restrict__ Wl, __half* __restrict__ pwh)
{
    const int i = blockIdx.x * 256 + threadIdx.x;
    if (i < D * D) {
        const float v = W[i];
        const __half h = __float2half_rn(v);
        Wh[i] = h;
        Wl[i] = __float2half_rn(v - __half2float(h));
        pwh[i] = __float2half_rn(pw[i]);
    }
}

// x [B,S,D] fp32 -> xTh [B,D,S] fp16
__global__ __launch_bounds__(256)
void transpose_half_kernel(const float* __restrict__ x, __half* __restrict__ xT)
{
    __shared__ float tile[32][33];
    const int b = blockIdx.z;
    const int s0 = blockIdx.x * 32;
    const int d0 = blockIdx.y * 32;
    const float* xb = x + (size_t)b * S * D;
    __half* xtb = xT + (size_t)b * S * D;
    const int tx = threadIdx.x & 31, ty = threadIdx.x >> 5;
    #pragma unroll
    for (int i = 0; i < 32; i += 8)
        tile[ty + i][tx] = xb[(size_t)(s0 + ty + i) * D + d0 + tx];
    __syncthreads();
    #pragma unroll
    for (int i = 0; i < 32; i += 8)
        xtb[(size_t)(d0 + ty + i) * S + s0 + tx] = __float2half_rn(tile[tx][ty + i]);
}

// ---------------------------------------------------------------------------
// Masked softmax: rows of s [B*S, S] fp32 -> a fp16 (diag masked)
// ---------------------------------------------------------------------------
__device__ __forceinline__ float warp_max(float v) {
    #pragma unroll
    for (int o = 16; o > 0; o >>= 1) v = fmaxf(v, __shfl_xor_sync(0xffffffffu, v, o));
    return v;
}
__device__ __forceinline__ float warp_sum(float v) {
    #pragma unroll
    for (int o = 16; o > 0; o >>= 1) v += __shfl_xor_sync(0xffffffffu, v, o);
    return v;
}

__global__ __launch_bounds__(256)
void softmax_mask_kernel(const float* __restrict__ s, __half* __restrict__ a)
{
    const int row  = blockIdx.x;
    const int diag = row & (S - 1);
    const float* p = s + (size_t)row * S;
    __half* q = a + (size_t)row * S;

    __shared__ float buf[S];
    __shared__ float red[8];
    const int tid = threadIdx.x;

    float mx = -CUDART_INF_F;
    for (int j = tid; j < S; j += 256) {
        float v = p[j];
        if (j == diag) v = -CUDART_INF_F;
        buf[j] = v;
        mx = fmaxf(mx, v);
    }
    mx = warp_max(mx);
    if ((tid & 31) == 0) red[tid >> 5] = mx;
    __syncthreads();
    if (tid == 0) {
        float m = red[0];
        #pragma unroll
        for (int w = 1; w < 8; ++w) m = fmaxf(m, red[w]);
        red[0] = m;
    }
    __syncthreads();
    mx = red[0];

    float sum = 0.f;
    for (int j = tid; j < S; j += 256) {
        const float e = __expf(buf[j] - mx);
        buf[j] = e;
        sum += e;
    }
    sum = warp_sum(sum);
    __syncthreads();
    if ((tid & 31) == 0) red[tid >> 5] = sum;
    __syncthreads();
    if (tid == 0) {
        float t = 0.f;
        #pragma unroll
        for (int w = 0; w < 8; ++w) t += red[w];
        red[0] = t;
    }
    __syncthreads();
    const float inv = 1.0f / red[0];
    for (int j = tid; j < S; j += 256) q[j] = __float2half_rn(buf[j] * inv);
}

// ---------------------------------------------------------------------------
// Launch
// ---------------------------------------------------------------------------
extern "C" void kernel_launch(void* const* d_in, const int* in_sizes, int n_in,
                              void* d_out, int out_size)
{
    const float* x  = (const float*)d_in[0];
    const float* W  = (const float*)d_in[1];
    const float* pw = (const float*)d_in[2];
    const float* pb = (const float*)d_in[3];
    float* out = (float*)d_out;

    __half *xh, *xl, *xTh, *Wh, *Wl, *pwh, *Wxh, *Wxl, *ah, *ch;
    float *sbuf;
    cudaGetSymbolAddress((void**)&xh,  g_xh);
    cudaGetSymbolAddress((void**)&xl,  g_xl);
    cudaGetSymbolAddress((void**)&xTh, g_xTh);
    cudaGetSymbolAddress((void**)&Wh,  g_Wh);
    cudaGetSymbolAddress((void**)&Wl,  g_Wl);
    cudaGetSymbolAddress((void**)&pwh, g_pwh);
    cudaGetSymbolAddress((void**)&Wxh, g_Wxh);
    cudaGetSymbolAddress((void**)&Wxl, g_Wxl);
    cudaGetSymbolAddress((void**)&ah,  g_ah);
    cudaGetSymbolAddress((void**)&ch,  g_ch);
    cudaGetSymbolAddress((void**)&sbuf, g_s);

    // smem: 3 pipeline stages; staged epilogues need >= 64KB for the fp32 tile
    constexpr int SMEM_SP3   = (int)(3 * TILE_B * 4);                 // 122880
    constexpr int SMEM_PLAIN_RAW = (int)(3 * TILE_B * 2);             //  61440
    constexpr int SMEM_PLAIN = SMEM_PLAIN_RAW > 65536 ? SMEM_PLAIN_RAW : 65536;
    cudaFuncSetAttribute(hgemm<true, 1>,  cudaFuncAttributeMaxDynamicSharedMemorySize, SMEM_SP3);
    cudaFuncSetAttribute(hgemm<true, 0>,  cudaFuncAttributeMaxDynamicSharedMemorySize, SMEM_SP3);
    cudaFuncSetAttribute(hgemm<false, 2>, cudaFuncAttributeMaxDynamicSharedMemorySize, SMEM_PLAIN);
    cudaFuncSetAttribute(hgemm<false, 3>, cudaFuncAttributeMaxDynamicSharedMemorySize, SMEM_PLAIN);

    const size_t SD = (size_t)S * D, SS = (size_t)S * S;

    // prep
    prep_x_kernel<<<(unsigned)(((size_t)B * S * D + 255) / 256), 256>>>(x, xh, xl);
    prep_w_kernel<<<(D * D + 255) / 256, 256>>>(W, pw, Wh, Wl, pwh);
    transpose_half_kernel<<<dim3(S / 32, D / 32, B), 256>>>(x, xTh);

    // GEMM1 (fp16x3): Wx = x @ W^T  -> split fp16 (Wxh, Wxl)
    hgemm<true, 1><<<dim3(D / 128, M_TOT / 128, 1), 256, SMEM_SP3>>>(
        xh, xl, Wh, Wl, nullptr, Wxh, Wxl, nullptr, nullptr,
        D, D, D, D, 0, 0, 0);

    // GEMM2 (fp16x3, batched): s[b] = Wx[b] @ x[b]^T -> fp32
    hgemm<true, 0><<<dim3(S / 128, S / 128, B), 256, SMEM_SP3>>>(
        Wxh, Wxl, xh, xl, sbuf, nullptr, nullptr, nullptr, nullptr,
        D, D, S, D, SD, SD, SS);

    // masked softmax -> fp16 a
    softmax_mask_kernel<<<B * S, 256>>>(sbuf, ah);

    // GEMM3 (fp16, batched): c[b] = a[b] @ x[b] -> fp16 ch   (B operand = xT)
    hgemm<false, 2><<<dim3(D / 128, S / 128, B), 256, SMEM_PLAIN>>>(
        ah, nullptr, xTh, nullptr, nullptr, ch, nullptr, nullptr, nullptr,
        S, S, D, S, SS, SD, SD);

    // GEMM4 (fp16 + epilogue): out = x + relu(c @ pw^T + pb)
    hgemm<false, 3><<<dim3(D / 128, M_TOT / 128, 1), 256, SMEM_PLAIN>>>(
        ch, nullptr, pwh, nullptr, out, nullptr, nullptr, pb, x,
        D, D, D, D, 0, 0, 0);
}

// round 6
// speedup vs baseline: 1.0733x; 1.0733x over previous
#include <cuda_runtime.h>
#include <cuda_fp16.h>
#include <mma.h>
#include <cstdint>
#include <math_constants.h>

using namespace nvcuda;

static constexpr int B = 8, S = 2048, D = 768;
static constexpr int M_TOT = B * S; // 16384

// ---------------------------------------------------------------------------
// Scratch (__device__ globals — allocation-free rule)
// ---------------------------------------------------------------------------
__device__ __half g_xh [(size_t)B * S * D];
__device__ __half g_xl [(size_t)B * S * D];
__device__ __half g_xTh[(size_t)B * S * D];   // [B, D, S]
__device__ __half g_Wh [D * D];
__device__ __half g_Wl [D * D];
__device__ __half g_pwh[D * D];
__device__ __half g_Wxh[(size_t)B * S * D];
__device__ __half g_Wxl[(size_t)B * S * D];
__device__ __half g_ah [(size_t)B * S * S];   // softmax output fp16
__device__ __half g_ch [(size_t)B * S * D];
__device__ float  g_s  [(size_t)B * S * S];   // logits fp32

// ---------------------------------------------------------------------------
// cp.async helpers
// ---------------------------------------------------------------------------
__device__ __forceinline__ uint32_t smem_u32(const void* p) {
    uint32_t a;
    asm("{ .reg .u64 t; cvta.to.shared.u64 t, %1; cvt.u32.u64 %0, t; }" : "=r"(a) : "l"(p));
    return a;
}
__device__ __forceinline__ void cp16(uint32_t saddr, const void* g) {
    asm volatile("cp.async.cg.shared.global [%0], [%1], 16;" :: "r"(saddr), "l"(g));
}
__device__ __forceinline__ void cp_commit() { asm volatile("cp.async.commit_group;" ::: "memory"); }
__device__ __forceinline__ void cp_wait1()  { asm volatile("cp.async.wait_group 1;" ::: "memory"); }

// ---------------------------------------------------------------------------
// hgemm: C[M,N] = A[M,K] * B[N,K]^T  (both operands K-contiguous fp16)
// CTA tile 256(M) x 128(N), BK=64, 2-stage cp.async, 512 threads
// (16 warps of 64x32 via wmma 16x16x16 — 4 warps per SMSP for pipe overlap).
// Smem rows padded to LDH=72 halves (144B stride — conflict-free ldmatrix).
// SP3: 3-pass compensated product (Ah*Bh + Ah*Bl + Al*Bh).
// EPI: 0 = fp32 C (direct wmma store); 1 = split fp16 (Ch+Cl);
//      2 = fp16 Ch; 3 = fp32 resid + relu(C + bias)
// ---------------------------------------------------------------------------
static constexpr int BK  = 64;
static constexpr int TM_CTA = 256;
static constexpr int TN_CTA = 128;
static constexpr int LDH = 72;                        // halves per smem row
static constexpr uint32_t AT_B = TM_CTA * LDH * 2;    // 36864 bytes
static constexpr uint32_t BT_B = TN_CTA * LDH * 2;    // 18432 bytes

template <bool SP3>
__device__ __forceinline__ void load_chunk(
    uint32_t sb, const __half* Ah, const __half* Al,
    const __half* Bh, const __half* Bl,
    int lda, int ldb, int rowBase, int colBase, int k0, int tid)
{
    const uint32_t sbB = sb + (SP3 ? 2 : 1) * AT_B;
    // A tiles: 256 rows x 8 granules = 2048 granules of 16B
    #pragma unroll
    for (int i = 0; i < 4; ++i) {
        const int g = tid + i * 512;
        const int r = g >> 3;
        const int c = g & 7;
        const uint32_t off = (uint32_t)(r * (LDH * 2) + c * 16);
        const size_t ga = (size_t)(rowBase + r) * lda + k0 + c * 8;
        cp16(sb + off, Ah + ga);
        if (SP3) cp16(sb + AT_B + off, Al + ga);
    }
    // B tiles: 128 rows x 8 granules = 1024 granules
    #pragma unroll
    for (int i = 0; i < 2; ++i) {
        const int g = tid + i * 512;
        const int r = g >> 3;
        const int c = g & 7;
        const uint32_t off = (uint32_t)(r * (LDH * 2) + c * 16);
        const size_t gb = (size_t)(colBase + r) * ldb + k0 + c * 8;
        cp16(sbB + off, Bh + gb);
        if (SP3) cp16(sbB + BT_B + off, Bl + gb);
    }
}

template <bool SP3>
__device__ __forceinline__ void compute_chunk(
    const __half* sm,
    wmma::fragment<wmma::accumulator, 16, 16, 16, float> acc[4][2],
    int warp_m, int warp_n)
{
    const __half* As  = sm;
    const __half* Als = sm + TM_CTA * LDH;
    const __half* Bs  = sm + (SP3 ? 2 : 1) * TM_CTA * LDH;
    const __half* Bls = Bs + TN_CTA * LDH;

    #pragma unroll
    for (int kk = 0; kk < BK / 16; ++kk) {
        wmma::fragment<wmma::matrix_b, 16, 16, 16, __half, wmma::col_major> bh[2], bl[2];
        wmma::fragment<wmma::matrix_a, 16, 16, 16, __half, wmma::row_major> ah[4], al[4];
        #pragma unroll
        for (int nj = 0; nj < 2; ++nj) {
            wmma::load_matrix_sync(bh[nj], Bs + (size_t)(warp_n + nj * 16) * LDH + kk * 16, LDH);
            if (SP3)
                wmma::load_matrix_sync(bl[nj], Bls + (size_t)(warp_n + nj * 16) * LDH + kk * 16, LDH);
        }
        #pragma unroll
        for (int mi = 0; mi < 4; ++mi) {
            wmma::load_matrix_sync(ah[mi], As + (size_t)(warp_m + mi * 16) * LDH + kk * 16, LDH);
            if (SP3)
                wmma::load_matrix_sync(al[mi], Als + (size_t)(warp_m + mi * 16) * LDH + kk * 16, LDH);
        }
        // Pass 1: Ah*Bh — 8 independent accumulators back-to-back
        #pragma unroll
        for (int mi = 0; mi < 4; ++mi)
            #pragma unroll
            for (int nj = 0; nj < 2; ++nj)
                wmma::mma_sync(acc[mi][nj], ah[mi], bh[nj], acc[mi][nj]);
        if (SP3) {
            #pragma unroll
            for (int mi = 0; mi < 4; ++mi)
                #pragma unroll
                for (int nj = 0; nj < 2; ++nj)
                    wmma::mma_sync(acc[mi][nj], ah[mi], bl[nj], acc[mi][nj]);
            #pragma unroll
            for (int mi = 0; mi < 4; ++mi)
                #pragma unroll
                for (int nj = 0; nj < 2; ++nj)
                    wmma::mma_sync(acc[mi][nj], al[mi], bh[nj], acc[mi][nj]);
        }
    }
}

template <bool SP3, int EPI>
__global__ __launch_bounds__(512, 1)
void hgemm(const __half* __restrict__ Ah, const __half* __restrict__ Al,
           const __half* __restrict__ Bh, const __half* __restrict__ Bl,
           float* __restrict__ Cf, __half* __restrict__ Ch, __half* __restrict__ Cl,
           const float* __restrict__ bias, const float* __restrict__ resid,
           int lda, int ldb, int ldc, int K,
           size_t sA, size_t sB, size_t sC)
{
    extern __shared__ char smem[];
    const uint32_t sb0 = smem_u32(smem);
    constexpr uint32_t BUF = (SP3 ? 2 : 1) * (AT_B + BT_B);

    const int tid = threadIdx.x, wid = tid >> 5;
    const int rowBase = blockIdx.y * TM_CTA;
    const int colBase = blockIdx.x * TN_CTA;
    const int warp_m = (wid >> 2) * 64;   // 0,64,128,192
    const int warp_n = (wid & 3) * 32;    // 0,32,64,96

    Ah += (size_t)blockIdx.z * sA;
    Bh += (size_t)blockIdx.z * sB;
    if (SP3) { Al += (size_t)blockIdx.z * sA; Bl += (size_t)blockIdx.z * sB; }

    wmma::fragment<wmma::accumulator, 16, 16, 16, float> acc[4][2];
    #pragma unroll
    for (int mi = 0; mi < 4; ++mi)
        #pragma unroll
        for (int nj = 0; nj < 2; ++nj)
            wmma::fill_fragment(acc[mi][nj], 0.0f);

    const int NK = K / BK;

    load_chunk<SP3>(sb0, Ah, Al, Bh, Bl, lda, ldb, rowBase, colBase, 0, tid);
    cp_commit();

    for (int ck = 0; ck < NK; ++ck) {
        if (ck + 1 < NK)
            load_chunk<SP3>(sb0 + ((ck + 1) & 1) * BUF, Ah, Al, Bh, Bl,
                            lda, ldb, rowBase, colBase, (ck + 1) * BK, tid);
        cp_commit();
        cp_wait1();
        __syncthreads();
        compute_chunk<SP3>((const __half*)(smem + (ck & 1) * BUF), acc, warp_m, warp_n);
        __syncthreads();
    }

    if (EPI == 0) {
        #pragma unroll
        for (int mi = 0; mi < 4; ++mi)
            #pragma unroll
            for (int nj = 0; nj < 2; ++nj) {
                float* dst = (Cf + (size_t)blockIdx.z * sC)
                           + (size_t)(rowBase + warp_m + mi * 16) * ldc
                           + colBase + warp_n + nj * 16;
                wmma::store_matrix_sync(dst, acc[mi][nj], ldc, wmma::mem_row_major);
            }
        return;
    }

    // staged epilogue: park the 256x128 fp32 tile in smem, then transform.
    float* stg = (float*)smem;
    #pragma unroll
    for (int mi = 0; mi < 4; ++mi)
        #pragma unroll
        for (int nj = 0; nj < 2; ++nj)
            wmma::store_matrix_sync(stg + (size_t)(warp_m + mi * 16) * 128 + warp_n + nj * 16,
                                    acc[mi][nj], 128, wmma::mem_row_major);
    __syncthreads();

    #pragma unroll
    for (int i = 0; i < 16; ++i) {
        const int idx = i * 512 + tid;   // 8192 float4 chunks (256x128 fp32)
        const int el = idx * 4;
        const int row = el >> 7;
        const int col = el & 127;
        const float4 v = *(const float4*)(stg + el);
        const size_t m = (size_t)(rowBase + row);
        const int n = colBase + col;
        if (EPI == 1) {
            __half* ChB = Ch + (size_t)blockIdx.z * sC;
            __half* ClB = Cl + (size_t)blockIdx.z * sC;
            const __half h0 = __float2half_rn(v.x), h1 = __float2half_rn(v.y);
            const __half h2 = __float2half_rn(v.z), h3 = __float2half_rn(v.w);
            *(__half2*)(ChB + m * ldc + n)     = __halves2half2(h0, h1);
            *(__half2*)(ChB + m * ldc + n + 2) = __halves2half2(h2, h3);
            *(__half2*)(ClB + m * ldc + n) =
                __halves2half2(__float2half_rn(v.x - __half2float(h0)),
                               __float2half_rn(v.y - __half2float(h1)));
            *(__half2*)(ClB + m * ldc + n + 2) =
                __halves2half2(__float2half_rn(v.z - __half2float(h2)),
                               __float2half_rn(v.w - __half2float(h3)));
        } else if (EPI == 2) {
            __half* ChB = Ch + (size_t)blockIdx.z * sC;
            *(__half2*)(ChB + m * ldc + n)     = __halves2half2(__float2half_rn(v.x), __float2half_rn(v.y));
            *(__half2*)(ChB + m * ldc + n + 2) = __halves2half2(__float2half_rn(v.z), __float2half_rn(v.w));
        } else { // EPI == 3
            const float4 bb = *(const float4*)(bias + n);
            const float4 rr = *(const float4*)(resid + m * ldc + n);
            float4 o;
            o.x = fmaxf(v.x + bb.x, 0.f) + rr.x;
            o.y = fmaxf(v.y + bb.y, 0.f) + rr.y;
            o.z = fmaxf(v.z + bb.z, 0.f) + rr.z;
            o.w = fmaxf(v.w + bb.w, 0.f) + rr.w;
            *(float4*)(Cf + m * ldc + n) = o;
        }
    }
}

// ---------------------------------------------------------------------------
// Prep kernels
// ---------------------------------------------------------------------------
__global__ __launch_bounds__(256)
void prep_x_kernel(const float* __restrict__ x, __half* __restrict__ xh, __half* __restrict__ xl)
{
    const size_t i = (size_t)blockIdx.x * 256 + threadIdx.x;
    const size_t n = (size_t)B * S * D;
    if (i < n) {
        const float v = x[i];
        const __half h = __float2half_rn(v);
        xh[i] = h;
        xl[i] = __float2half_rn(v - __half2float(h));
    }
}

__global__ __launch_bounds__(256)
void prep_w_kernel(const float* __restrict__ W, const float* __restrict__ pw,
                   __half* __restrict__ Wh, __half* __restrict__ Wl, __half* __restrict__ pwh)
{
    const int i = blockIdx.x * 256 + threadIdx.x;
    if (i < D * D) {
        const float v = W[i];
        const __half h = __float2half_rn(v);
        Wh[i] = h;
        Wl[i] = __float2half_rn(v - __half2float(h));
        pwh[i] = __float2half_rn(pw[i]);
    }
}

// x [B,S,D] fp32 -> xTh [B,D,S] fp16
__global__ __launch_bounds__(256)
void transpose_half_kernel(const float* __restrict__ x, __half* __restrict__ xT)
{
    __shared__ float tile[32][33];
    const int b = blockIdx.z;
    const int s0 = blockIdx.x * 32;
    const int d0 = blockIdx.y * 32;
    const float* xb = x + (size_t)b * S * D;
    __half* xtb = xT + (size_t)b * S * D;
    const int tx = threadIdx.x & 31, ty = threadIdx.x >> 5;
    #pragma unroll
    for (int i = 0; i < 32; i += 8)
        tile[ty + i][tx] = xb[(size_t)(s0 + ty + i) * D + d0 + tx];
    __syncthreads();
    #pragma unroll
    for (int i = 0; i < 32; i += 8)
        xtb[(size_t)(d0 + ty + i) * S + s0 + tx] = __float2half_rn(tile[tx][ty + i]);
}

// ---------------------------------------------------------------------------
// Masked softmax: rows of s [B*S, S] fp32 -> a fp16 (diag masked)
// ---------------------------------------------------------------------------
__device__ __forceinline__ float warp_max(float v) {
    #pragma unroll
    for (int o = 16; o > 0; o >>= 1) v = fmaxf(v, __shfl_xor_sync(0xffffffffu, v, o));
    return v;
}
__device__ __forceinline__ float warp_sum(float v) {
    #pragma unroll
    for (int o = 16; o > 0; o >>= 1) v += __shfl_xor_sync(0xffffffffu, v, o);
    return v;
}

__global__ __launch_bounds__(256)
void softmax_mask_kernel(const float* __restrict__ s, __half* __restrict__ a)
{
    const int row  = blockIdx.x;
    const int diag = row & (S - 1);
    const float* p = s + (size_t)row * S;
    __half* q = a + (size_t)row * S;

    __shared__ float buf[S];
    __shared__ float red[8];
    const int tid = threadIdx.x;

    float mx = -CUDART_INF_F;
    for (int j = tid; j < S; j += 256) {
        float v = p[j];
        if (j == diag) v = -CUDART_INF_F;
        buf[j] = v;
        mx = fmaxf(mx, v);
    }
    mx = warp_max(mx);
    if ((tid & 31) == 0) red[tid >> 5] = mx;
    __syncthreads();
    if (tid == 0) {
        float m = red[0];
        #pragma unroll
        for (int w = 1; w < 8; ++w) m = fmaxf(m, red[w]);
        red[0] = m;
    }
    __syncthreads();
    mx = red[0];

    float sum = 0.f;
    for (int j = tid; j < S; j += 256) {
        const float e = __expf(buf[j] - mx);
        buf[j] = e;
        sum += e;
    }
    sum = warp_sum(sum);
    __syncthreads();
    if ((tid & 31) == 0) red[tid >> 5] = sum;
    __syncthreads();
    if (tid == 0) {
        float t = 0.f;
        #pragma unroll
        for (int w = 0; w < 8; ++w) t += red[w];
        red[0] = t;
    }
    __syncthreads();
    const float inv = 1.0f / red[0];
    for (int j = tid; j < S; j += 256) q[j] = __float2half_rn(buf[j] * inv);
}

// ---------------------------------------------------------------------------
// Launch
// ---------------------------------------------------------------------------
extern "C" void kernel_launch(void* const* d_in, const int* in_sizes, int n_in,
                              void* d_out, int out_size)
{
    const float* x  = (const float*)d_in[0];
    const float* W  = (const float*)d_in[1];
    const float* pw = (const float*)d_in[2];
    const float* pb = (const float*)d_in[3];
    float* out = (float*)d_out;

    __half *xh, *xl, *xTh, *Wh, *Wl, *pwh, *Wxh, *Wxl, *ah, *ch;
    float *sbuf;
    cudaGetSymbolAddress((void**)&xh,  g_xh);
    cudaGetSymbolAddress((void**)&xl,  g_xl);
    cudaGetSymbolAddress((void**)&xTh, g_xTh);
    cudaGetSymbolAddress((void**)&Wh,  g_Wh);
    cudaGetSymbolAddress((void**)&Wl,  g_Wl);
    cudaGetSymbolAddress((void**)&pwh, g_pwh);
    cudaGetSymbolAddress((void**)&Wxh, g_Wxh);
    cudaGetSymbolAddress((void**)&Wxl, g_Wxl);
    cudaGetSymbolAddress((void**)&ah,  g_ah);
    cudaGetSymbolAddress((void**)&ch,  g_ch);
    cudaGetSymbolAddress((void**)&sbuf, g_s);

    // smem: 2 pipeline stages; staged epilogues need 128KB for the 256x128 fp32 tile
    constexpr int SMEM_SP3   = (int)(2 * 2 * (AT_B + BT_B));  // 221184
    constexpr int SMEM_PLAIN_RAW = (int)(2 * (AT_B + BT_B));  // 110592
    constexpr int SMEM_PLAIN = SMEM_PLAIN_RAW > 131072 ? SMEM_PLAIN_RAW : 131072;
    cudaFuncSetAttribute(hgemm<true, 1>,  cudaFuncAttributeMaxDynamicSharedMemorySize, SMEM_SP3);
    cudaFuncSetAttribute(hgemm<true, 0>,  cudaFuncAttributeMaxDynamicSharedMemorySize, SMEM_SP3);
    cudaFuncSetAttribute(hgemm<false, 2>, cudaFuncAttributeMaxDynamicSharedMemorySize, SMEM_PLAIN);
    cudaFuncSetAttribute(hgemm<false, 3>, cudaFuncAttributeMaxDynamicSharedMemorySize, SMEM_PLAIN);

    const size_t SD = (size_t)S * D, SS = (size_t)S * S;

    // prep
    prep_x_kernel<<<(unsigned)(((size_t)B * S * D + 255) / 256), 256>>>(x, xh, xl);
    prep_w_kernel<<<(D * D + 255) / 256, 256>>>(W, pw, Wh, Wl, pwh);
    transpose_half_kernel<<<dim3(S / 32, D / 32, B), 256>>>(x, xTh);

    // GEMM1 (fp16x3): Wx = x @ W^T  -> split fp16 (Wxh, Wxl)
    hgemm<true, 1><<<dim3(D / TN_CTA, M_TOT / TM_CTA, 1), 512, SMEM_SP3>>>(
        xh, xl, Wh, Wl, nullptr, Wxh, Wxl, nullptr, nullptr,
        D, D, D, D, 0, 0, 0);

    // GEMM2 (fp16x3, batched): s[b] = Wx[b] @ x[b]^T -> fp32
    hgemm<true, 0><<<dim3(S / TN_CTA, S / TM_CTA, B), 512, SMEM_SP3>>>(
        Wxh, Wxl, xh, xl, sbuf, nullptr, nullptr, nullptr, nullptr,
        D, D, S, D, SD, SD, SS);

    // masked softmax -> fp16 a
    softmax_mask_kernel<<<B * S, 256>>>(sbuf, ah);

    // GEMM3 (fp16, batched): c[b] = a[b] @ x[b] -> fp16 ch   (B operand = xT)
    hgemm<false, 2><<<dim3(D / TN_CTA, S / TM_CTA, B), 512, SMEM_PLAIN>>>(
        ah, nullptr, xTh, nullptr, nullptr, ch, nullptr, nullptr, nullptr,
        S, S, D, S, SS, SD, SD);

    // GEMM4 (fp16 + epilogue): out = x + relu(c @ pw^T + pb)
    hgemm<false, 3><<<dim3(D / TN_CTA, M_TOT / TM_CTA, 1), 512, SMEM_PLAIN>>>(
        ch, nullptr, pwh, nullptr, out, nullptr, nullptr, pb, x,
        D, D, D, D, 0, 0, 0);
}

// round 7
// speedup vs baseline: 1.1381x; 1.0604x over previous
#include <cuda_runtime.h>
#include <cuda_fp16.h>
#include <mma.h>
#include <cstdint>
#include <math_constants.h>

using namespace nvcuda;

static constexpr int B = 8, S = 2048, D = 768;
static constexpr int M_TOT = B * S;   // 16384
static constexpr int NTILE = S / 128; // 16 key tiles per row

// ---------------------------------------------------------------------------
// Scratch (__device__ globals — allocation-free rule)
// ---------------------------------------------------------------------------
__device__ __half g_xh [(size_t)B * S * D];
__device__ __half g_xl [(size_t)B * S * D];
__device__ __half g_xTh[(size_t)B * S * D];   // [B, D, S]
__device__ __half g_Wh [D * D];
__device__ __half g_Wl [D * D];
__device__ __half g_pwh[D * D];
__device__ __half g_Wxh[(size_t)B * S * D];
__device__ __half g_Wxl[(size_t)B * S * D];
__device__ __half g_ah [(size_t)B * S * S];   // p, then (in place) softmax a, fp16
__device__ __half g_ch [(size_t)B * S * D];
__device__ float2 g_st [(size_t)B * S * NTILE]; // per-(row,tile) partial (max, sumexp)

// ---------------------------------------------------------------------------
// cp.async helpers
// ---------------------------------------------------------------------------
__device__ __forceinline__ uint32_t smem_u32(const void* p) {
    uint32_t a;
    asm("{ .reg .u64 t; cvta.to.shared.u64 t, %1; cvt.u32.u64 %0, t; }" : "=r"(a) : "l"(p));
    return a;
}
__device__ __forceinline__ void cp16(uint32_t saddr, const void* g) {
    asm volatile("cp.async.cg.shared.global [%0], [%1], 16;" :: "r"(saddr), "l"(g));
}
__device__ __forceinline__ void cp_commit() { asm volatile("cp.async.commit_group;" ::: "memory"); }
__device__ __forceinline__ void cp_wait1()  { asm volatile("cp.async.wait_group 1;" ::: "memory"); }

__device__ __forceinline__ float wmax(float v) {
    #pragma unroll
    for (int o = 16; o > 0; o >>= 1) v = fmaxf(v, __shfl_xor_sync(0xffffffffu, v, o));
    return v;
}
__device__ __forceinline__ float wsum(float v) {
    #pragma unroll
    for (int o = 16; o > 0; o >>= 1) v += __shfl_xor_sync(0xffffffffu, v, o);
    return v;
}

// ---------------------------------------------------------------------------
// hgemm: C[M,N] = A[M,K] * B[N,K]^T  (both operands K-contiguous fp16)
// CTA tile 256(M) x 128(N), BK=64, 2-stage cp.async, 512 threads
// (16 warps of 64x32 via wmma 16x16x16 — 4 warps per SMSP).
// Smem rows padded to LDH=72 halves (144B stride — conflict-free ldmatrix).
// SP3: 3-pass compensated product (Ah*Bh + Ah*Bl + Al*Bh).
// EPI: 1 = split fp16 (Ch+Cl); 2 = fp16 Ch; 3 = fp32 resid + relu(C + bias);
//      4 = fused partial softmax: mask diag, per-row tile (m,z) -> stats,
//          p = exp(v-m) fp16 -> Ch
// ---------------------------------------------------------------------------
static constexpr int BK  = 64;
static constexpr int TM_CTA = 256;
static constexpr int TN_CTA = 128;
static constexpr int LDH = 72;                        // halves per smem row
static constexpr uint32_t AT_B = TM_CTA * LDH * 2;    // 36864 bytes
static constexpr uint32_t BT_B = TN_CTA * LDH * 2;    // 18432 bytes
static constexpr int LDS4 = 132;                      // fp32 stage stride (EPI4)

template <bool SP3>
__device__ __forceinline__ void load_chunk(
    uint32_t sb, const __half* Ah, const __half* Al,
    const __half* Bh, const __half* Bl,
    int lda, int ldb, int rowBase, int colBase, int k0, int tid)
{
    const uint32_t sbB = sb + (SP3 ? 2 : 1) * AT_B;
    #pragma unroll
    for (int i = 0; i < 4; ++i) {
        const int g = tid + i * 512;
        const int r = g >> 3;
        const int c = g & 7;
        const uint32_t off = (uint32_t)(r * (LDH * 2) + c * 16);
        const size_t ga = (size_t)(rowBase + r) * lda + k0 + c * 8;
        cp16(sb + off, Ah + ga);
        if (SP3) cp16(sb + AT_B + off, Al + ga);
    }
    #pragma unroll
    for (int i = 0; i < 2; ++i) {
        const int g = tid + i * 512;
        const int r = g >> 3;
        const int c = g & 7;
        const uint32_t off = (uint32_t)(r * (LDH * 2) + c * 16);
        const size_t gb = (size_t)(colBase + r) * ldb + k0 + c * 8;
        cp16(sbB + off, Bh + gb);
        if (SP3) cp16(sbB + BT_B + off, Bl + gb);
    }
}

template <bool SP3>
__device__ __forceinline__ void compute_chunk(
    const __half* sm,
    wmma::fragment<wmma::accumulator, 16, 16, 16, float> acc[4][2],
    int warp_m, int warp_n)
{
    const __half* As  = sm;
    const __half* Als = sm + TM_CTA * LDH;
    const __half* Bs  = sm + (SP3 ? 2 : 1) * TM_CTA * LDH;
    const __half* Bls = Bs + TN_CTA * LDH;

    #pragma unroll
    for (int kk = 0; kk < BK / 16; ++kk) {
        wmma::fragment<wmma::matrix_b, 16, 16, 16, __half, wmma::col_major> bh[2], bl[2];
        wmma::fragment<wmma::matrix_a, 16, 16, 16, __half, wmma::row_major> ah[4], al[4];
        #pragma unroll
        for (int nj = 0; nj < 2; ++nj) {
            wmma::load_matrix_sync(bh[nj], Bs + (size_t)(warp_n + nj * 16) * LDH + kk * 16, LDH);
            if (SP3)
                wmma::load_matrix_sync(bl[nj], Bls + (size_t)(warp_n + nj * 16) * LDH + kk * 16, LDH);
        }
        #pragma unroll
        for (int mi = 0; mi < 4; ++mi) {
            wmma::load_matrix_sync(ah[mi], As + (size_t)(warp_m + mi * 16) * LDH + kk * 16, LDH);
            if (SP3)
                wmma::load_matrix_sync(al[mi], Als + (size_t)(warp_m + mi * 16) * LDH + kk * 16, LDH);
        }
        #pragma unroll
        for (int mi = 0; mi < 4; ++mi)
            #pragma unroll
            for (int nj = 0; nj < 2; ++nj)
                wmma::mma_sync(acc[mi][nj], ah[mi], bh[nj], acc[mi][nj]);
        if (SP3) {
            #pragma unroll
            for (int mi = 0; mi < 4; ++mi)
                #pragma unroll
                for (int nj = 0; nj < 2; ++nj)
                    wmma::mma_sync(acc[mi][nj], ah[mi], bl[nj], acc[mi][nj]);
            #pragma unroll
            for (int mi = 0; mi < 4; ++mi)
                #pragma unroll
                for (int nj = 0; nj < 2; ++nj)
                    wmma::mma_sync(acc[mi][nj], al[mi], bh[nj], acc[mi][nj]);
        }
    }
}

template <bool SP3, int EPI>
__global__ __launch_bounds__(512, 1)
void hgemm(const __half* __restrict__ Ah, const __half* __restrict__ Al,
           const __half* __restrict__ Bh, const __half* __restrict__ Bl,
           float* __restrict__ Cf, __half* __restrict__ Ch, __half* __restrict__ Cl,
           const float* __restrict__ bias, const float* __restrict__ resid,
           float2* __restrict__ stats,
           int lda, int ldb, int ldc, int K,
           size_t sA, size_t sB, size_t sC)
{
    extern __shared__ char smem[];
    const uint32_t sb0 = smem_u32(smem);
    constexpr uint32_t BUF = (SP3 ? 2 : 1) * (AT_B + BT_B);

    const int tid = threadIdx.x, wid = tid >> 5, lane = tid & 31;
    const int rowBase = blockIdx.y * TM_CTA;
    const int colBase = blockIdx.x * TN_CTA;
    const int warp_m = (wid >> 2) * 64;   // 0,64,128,192
    const int warp_n = (wid & 3) * 32;    // 0,32,64,96

    Ah += (size_t)blockIdx.z * sA;
    Bh += (size_t)blockIdx.z * sB;
    if (SP3) { Al += (size_t)blockIdx.z * sA; Bl += (size_t)blockIdx.z * sB; }

    wmma::fragment<wmma::accumulator, 16, 16, 16, float> acc[4][2];
    #pragma unroll
    for (int mi = 0; mi < 4; ++mi)
        #pragma unroll
        for (int nj = 0; nj < 2; ++nj)
            wmma::fill_fragment(acc[mi][nj], 0.0f);

    const int NK = K / BK;

    load_chunk<SP3>(sb0, Ah, Al, Bh, Bl, lda, ldb, rowBase, colBase, 0, tid);
    cp_commit();

    for (int ck = 0; ck < NK; ++ck) {
        if (ck + 1 < NK)
            load_chunk<SP3>(sb0 + ((ck + 1) & 1) * BUF, Ah, Al, Bh, Bl,
                            lda, ldb, rowBase, colBase, (ck + 1) * BK, tid);
        cp_commit();
        cp_wait1();
        __syncthreads();
        compute_chunk<SP3>((const __half*)(smem + (ck & 1) * BUF), acc, warp_m, warp_n);
        __syncthreads();
    }

    if (EPI == 4) {
        // ---- fused partial softmax (GEMM2) ----
        float* stg = (float*)smem;   // 256 x 128 fp32, stride LDS4=132
        #pragma unroll
        for (int mi = 0; mi < 4; ++mi)
            #pragma unroll
            for (int nj = 0; nj < 2; ++nj)
                wmma::store_matrix_sync(stg + (size_t)(warp_m + mi * 16) * LDS4 + warp_n + nj * 16,
                                        acc[mi][nj], LDS4, wmma::mem_row_major);
        __syncthreads();

        __half* pB = Ch + (size_t)blockIdx.z * sC;
        // warp wid reduces rows [wid*16, wid*16+16)
        #pragma unroll
        for (int rr = 0; rr < 16; ++rr) {
            const int r = wid * 16 + rr;
            const int q = rowBase + r;                 // batch-local query index
            float v[4];
            #pragma unroll
            for (int k = 0; k < 4; ++k) {
                const int c = lane + 32 * k;
                float t = stg[(size_t)r * LDS4 + c];
                if (q == colBase + c) t = -CUDART_INF_F;   // mask diagonal
                v[k] = t;
            }
            float m = fmaxf(fmaxf(v[0], v[1]), fmaxf(v[2], v[3]));
            m = wmax(m);
            float e[4], zs = 0.f;
            #pragma unroll
            for (int k = 0; k < 4; ++k) { e[k] = __expf(v[k] - m); zs += e[k]; }
            const float z = wsum(zs);
            #pragma unroll
            for (int k = 0; k < 4; ++k)
                pB[(size_t)q * ldc + colBase + lane + 32 * k] = __float2half_rn(e[k]);
            if (lane == 0)
                stats[((size_t)blockIdx.z * S + q) * NTILE + (colBase >> 7)] = make_float2(m, z);
        }
        return;
    }

    // staged epilogue (EPI 1/2/3): park the 256x128 fp32 tile in smem, transform.
    float* stg = (float*)smem;
    #pragma unroll
    for (int mi = 0; mi < 4; ++mi)
        #pragma unroll
        for (int nj = 0; nj < 2; ++nj)
            wmma::store_matrix_sync(stg + (size_t)(warp_m + mi * 16) * 128 + warp_n + nj * 16,
                                    acc[mi][nj], 128, wmma::mem_row_major);
    __syncthreads();

    #pragma unroll
    for (int i = 0; i < 16; ++i) {
        const int idx = i * 512 + tid;   // 8192 float4 chunks (256x128 fp32)
        const int el = idx * 4;
        const int row = el >> 7;
        const int col = el & 127;
        const float4 v = *(const float4*)(stg + el);
        const size_t m = (size_t)(rowBase + row);
        const int n = colBase + col;
        if (EPI == 1) {
            __half* ChB = Ch + (size_t)blockIdx.z * sC;
            __half* ClB = Cl + (size_t)blockIdx.z * sC;
            const __half h0 = __float2half_rn(v.x), h1 = __float2half_rn(v.y);
            const __half h2 = __float2half_rn(v.z), h3 = __float2half_rn(v.w);
            *(__half2*)(ChB + m * ldc + n)     = __halves2half2(h0, h1);
            *(__half2*)(ChB + m * ldc + n + 2) = __halves2half2(h2, h3);
            *(__half2*)(ClB + m * ldc + n) =
                __halves2half2(__float2half_rn(v.x - __half2float(h0)),
                               __float2half_rn(v.y - __half2float(h1)));
            *(__half2*)(ClB + m * ldc + n + 2) =
                __halves2half2(__float2half_rn(v.z - __half2float(h2)),
                               __float2half_rn(v.w - __half2float(h3)));
        } else if (EPI == 2) {
            __half* ChB = Ch + (size_t)blockIdx.z * sC;
            *(__half2*)(ChB + m * ldc + n)     = __halves2half2(__float2half_rn(v.x), __float2half_rn(v.y));
            *(__half2*)(ChB + m * ldc + n + 2) = __halves2half2(__float2half_rn(v.z), __float2half_rn(v.w));
        } else { // EPI == 3
            const float4 bb = *(const float4*)(bias + n);
            const float4 rr = *(const float4*)(resid + m * ldc + n);
            float4 o;
            o.x = fmaxf(v.x + bb.x, 0.f) + rr.x;
            o.y = fmaxf(v.y + bb.y, 0.f) + rr.y;
            o.z = fmaxf(v.z + bb.z, 0.f) + rr.z;
            o.w = fmaxf(v.w + bb.w, 0.f) + rr.w;
            *(float4*)(Cf + m * ldc + n) = o;
        }
    }
}

// ---------------------------------------------------------------------------
// softmax finalize: combine tile stats, rescale p -> a in place (fp16)
// one block (128 threads) per row
// ---------------------------------------------------------------------------
__global__ __launch_bounds__(128)
void softmax_finalize(__half* __restrict__ p, const float2* __restrict__ st)
{
    const size_t row = blockIdx.x;     // 0..B*S-1
    __shared__ float sc[NTILE];
    const int tid = threadIdx.x;

    if (tid == 0) {
        float2 t[NTILE];
        #pragma unroll
        for (int i = 0; i < NTILE; ++i) t[i] = st[row * NTILE + i];
        float M = t[0].x;
        #pragma unroll
        for (int i = 1; i < NTILE; ++i) M = fmaxf(M, t[i].x);
        float Z = 0.f;
        #pragma unroll
        for (int i = 0; i < NTILE; ++i) Z += t[i].y * __expf(t[i].x - M);
        const float inv = 1.0f / Z;
        #pragma unroll
        for (int i = 0; i < NTILE; ++i) sc[i] = __expf(t[i].x - M) * inv;
    }
    __syncthreads();

    __half2* pr = (__half2*)(p + row * S);
    #pragma unroll
    for (int i = tid; i < S / 2; i += 128) {
        const float s = sc[i >> 6];            // (2*i)/128
        const __half2 v = pr[i];
        pr[i] = __floats2half2_rn(__low2float(v) * s, __high2float(v) * s);
    }
}

// ---------------------------------------------------------------------------
// Prep kernels
// ---------------------------------------------------------------------------
__global__ __launch_bounds__(256)
void prep_x_kernel(const float* __restrict__ x, __half* __restrict__ xh, __half* __restrict__ xl)
{
    const size_t i = (size_t)blockIdx.x * 256 + threadIdx.x;
    const size_t n = (size_t)B * S * D;
    if (i < n) {
        const float v = x[i];
        const __half h = __float2half_rn(v);
        xh[i] = h;
        xl[i] = __float2half_rn(v - __half2float(h));
    }
}

__global__ __launch_bounds__(256)
void prep_w_kernel(const float* __restrict__ W, const float* __restrict__ pw,
                   __half* __restrict__ Wh, __half* __restrict__ Wl, __half* __restrict__ pwh)
{
    const int i = blockIdx.x * 256 + threadIdx.x;
    if (i < D * D) {
        const float v = W[i];
        const __half h = __float2half_rn(v);
        Wh[i] = h;
        Wl[i] = __float2half_rn(v - __half2float(h));
        pwh[i] = __float2half_rn(pw[i]);
    }
}

// x [B,S,D] fp32 -> xTh [B,D,S] fp16
__global__ __launch_bounds__(256)
void transpose_half_kernel(const float* __restrict__ x, __half* __restrict__ xT)
{
    __shared__ float tile[32][33];
    const int b = blockIdx.z;
    const int s0 = blockIdx.x * 32;
    const int d0 = blockIdx.y * 32;
    const float* xb = x + (size_t)b * S * D;
    __half* xtb = xT + (size_t)b * S * D;
    const int tx = threadIdx.x & 31, ty = threadIdx.x >> 5;
    #pragma unroll
    for (int i = 0; i < 32; i += 8)
        tile[ty + i][tx] = xb[(size_t)(s0 + ty + i) * D + d0 + tx];
    __syncthreads();
    #pragma unroll
    for (int i = 0; i < 32; i += 8)
        xtb[(size_t)(d0 + ty + i) * S + s0 + tx] = __float2half_rn(tile[tx][ty + i]);
}

// ---------------------------------------------------------------------------
// Launch
// ---------------------------------------------------------------------------
extern "C" void kernel_launch(void* const* d_in, const int* in_sizes, int n_in,
                              void* d_out, int out_size)
{
    const float* x  = (const float*)d_in[0];
    const float* W  = (const float*)d_in[1];
    const float* pw = (const float*)d_in[2];
    const float* pb = (const float*)d_in[3];
    float* out = (float*)d_out;

    __half *xh, *xl, *xTh, *Wh, *Wl, *pwh, *Wxh, *Wxl, *ah, *ch;
    float2* st;
    cudaGetSymbolAddress((void**)&xh,  g_xh);
    cudaGetSymbolAddress((void**)&xl,  g_xl);
    cudaGetSymbolAddress((void**)&xTh, g_xTh);
    cudaGetSymbolAddress((void**)&Wh,  g_Wh);
    cudaGetSymbolAddress((void**)&Wl,  g_Wl);
    cudaGetSymbolAddress((void**)&pwh, g_pwh);
    cudaGetSymbolAddress((void**)&Wxh, g_Wxh);
    cudaGetSymbolAddress((void**)&Wxl, g_Wxl);
    cudaGetSymbolAddress((void**)&ah,  g_ah);
    cudaGetSymbolAddress((void**)&ch,  g_ch);
    cudaGetSymbolAddress((void**)&st,  g_st);

    constexpr int SMEM_SP3   = (int)(2 * 2 * (AT_B + BT_B));  // 221184
    constexpr int SMEM_PLAIN_RAW = (int)(2 * (AT_B + BT_B));  // 110592
    constexpr int SMEM_PLAIN = SMEM_PLAIN_RAW > 131072 ? SMEM_PLAIN_RAW : 131072;
    cudaFuncSetAttribute(hgemm<true, 1>,  cudaFuncAttributeMaxDynamicSharedMemorySize, SMEM_SP3);
    cudaFuncSetAttribute(hgemm<true, 4>,  cudaFuncAttributeMaxDynamicSharedMemorySize, SMEM_SP3);
    cudaFuncSetAttribute(hgemm<false, 2>, cudaFuncAttributeMaxDynamicSharedMemorySize, SMEM_PLAIN);
    cudaFuncSetAttribute(hgemm<false, 3>, cudaFuncAttributeMaxDynamicSharedMemorySize, SMEM_PLAIN);

    const size_t SD = (size_t)S * D, SS = (size_t)S * S;

    // prep
    prep_x_kernel<<<(unsigned)(((size_t)B * S * D + 255) / 256), 256>>>(x, xh, xl);
    prep_w_kernel<<<(D * D + 255) / 256, 256>>>(W, pw, Wh, Wl, pwh);
    transpose_half_kernel<<<dim3(S / 32, D / 32, B), 256>>>(x, xTh);

    // GEMM1 (fp16x3): Wx = x @ W^T  -> split fp16 (Wxh, Wxl)
    hgemm<true, 1><<<dim3(D / TN_CTA, M_TOT / TM_CTA, 1), 512, SMEM_SP3>>>(
        xh, xl, Wh, Wl, nullptr, Wxh, Wxl, nullptr, nullptr, nullptr,
        D, D, D, D, 0, 0, 0);

    // GEMM2 (fp16x3, batched) + fused partial softmax:
    //   p[b] = exp(masked(Wx[b] @ x[b]^T) - m_tile)  (fp16), stats -> g_st
    hgemm<true, 4><<<dim3(S / TN_CTA, S / TM_CTA, B), 512, SMEM_SP3>>>(
        Wxh, Wxl, xh, xl, nullptr, ah, nullptr, nullptr, nullptr, st,
        D, D, S, D, SD, SD, SS);

    // combine tile stats, rescale p -> a in place
    softmax_finalize<<<B * S, 128>>>(ah, st);

    // GEMM3 (fp16, batched): c[b] = a[b] @ x[b] -> fp16 ch   (B operand = xT)
    hgemm<false, 2><<<dim3(D / TN_CTA, S / TM_CTA, B), 512, SMEM_PLAIN>>>(
        ah, nullptr, xTh, nullptr, nullptr, ch, nullptr, nullptr, nullptr, nullptr,
        S, S, D, S, SS, SD, SD);

    // GEMM4 (fp16 + epilogue): out = x + relu(c @ pw^T + pb)
    hgemm<false, 3><<<dim3(D / TN_CTA, M_TOT / TM_CTA, 1), 512, SMEM_PLAIN>>>(
        ch, nullptr, pwh, nullptr, out, nullptr, nullptr, pb, x, nullptr,
        D, D, D, D, 0, 0, 0);
}